// round 8
// baseline (speedup 1.0000x reference)
#include <cuda_runtime.h>
#include <cuda_bf16.h>
#include <cstdint>

// Problem shapes (fixed by setup_inputs): B=4, N=128, C_IN=C_OUT=32, X=3.
#define BZ 4
#define NN 128

// ---------------------------------------------------------------------------
// Scratch + sync state (no allocations allowed -> __device__ globals).
// All counters/flags are reset by the kernel itself before exit, so every
// graph replay starts from the same (zero) state. Deterministic: computed
// values do not depend on which block happens to finish last.
// ---------------------------------------------------------------------------
__device__ float4 g_base[BZ][NN][32];     // per-(z,c) base sums [b][k], 256 KB
__device__ float  g_W12g[9][32][32];      // W12[yx][i][k]
__device__ float  g_U[BZ][512];           // U0[32] | U1[96] | U2[96] | U3[288]
__device__ int    g_cnt[BZ];              // phase-A arrivals per z
__device__ int    g_cnt2[BZ];             // post-U readers per z (for reset)
__device__ int    g_flag[BZ];             // U-ready flag per z
__device__ int    g_w12cnt;               // W12 blocks done
__device__ int    g_cnt3;                 // middle blocks past w12 wait (for reset)

// Robust scalar load: handles int32 or float32 encodings of n_norm.
__device__ __forceinline__ float load_scalar_f(const void* p) {
    int iv = *(const int*)p;
    int ex = (iv >> 23) & 0xFF;
    if (ex > 60 && ex < 200) return __int_as_float(iv);
    return (float)iv;
}

// ---------------------------------------------------------------------------
// Single fused kernel. grid = BZ*NN + 9 blocks, 256 threads.
//   blocks [512..520]: W12[yx] = W2[y] @ W1[x]  (no data deps; runs alongside A)
//   blocks [0..511] (za = z*128 + c):
//     phase A: base sums for (z,c) -> g_base  (the 8 MB feature read)
//     last-arriving block per z: M reduce + U coefficients -> g_U, raise flag
//     all blocks of z: wait flag, expand row (z, a=c) -> out (8 MB write)
// ---------------------------------------------------------------------------
__global__ void __launch_bounds__(256, 4)
k_fused(const float* __restrict__ feat, const float* __restrict__ geo,
        const float* __restrict__ W1, const float* __restrict__ W2,
        const void* __restrict__ n_norm_ptr, float* __restrict__ out) {
    int blk = blockIdx.x;
    int t = threadIdx.x;  // 256

    // ---------------- W12 producer blocks ----------------
    if (blk >= BZ * NN) {
        int yx = blk - BZ * NN;     // 0..8
        int y = yx / 3, x = yx - y * 3;
        #pragma unroll
        for (int r = 0; r < 4; r++) {
            int idx = t + r * 256;          // i*32 + k
            int i = idx >> 5, k = idx & 31;
            const float* w2r = W2 + (y * 32 + i) * 32;   // W2[y][i][j]
            const float* w1c = W1 + x * 1024 + k;        // W1[x][j][k]
            float acc = 0.f;
            #pragma unroll
            for (int j = 0; j < 32; j++) acc = fmaf(w2r[j], w1c[j * 32], acc);
            g_W12g[yx][i][k] = acc;
        }
        __threadfence();
        __syncthreads();
        if (t == 0) atomicAdd(&g_w12cnt, 1);
        return;
    }

    // ---------------- za blocks ----------------
    int z = blk >> 7;
    int c = blk & (NN - 1);
    int kq   = t & 7;       // float4 index within 32-float k-row
    int dgrp = t >> 3;      // 0..31

    __shared__ float  sgeo[3][NN];     // geo[z] transposed [comp][d]
    __shared__ float4 smq[4][32][8];   // [comp][dgrp][kq], 16 KB
    __shared__ float  red[4][32];
    __shared__ float  sM[512];         // 16 moment rows of 32
    __shared__ float  sU[512];
    __shared__ float4 V0q[8];
    __shared__ float4 V1q[3][8];
    __shared__ int    s_last;

    for (int idx = t; idx < NN * 3; idx += 256) {
        int d = idx / 3, comp = idx - d * 3;
        sgeo[comp][d] = geo[z * NN * 3 + idx];
    }
    __syncthreads();

    // ---- Phase A: base sums over d ----
    const float4* f4 = (const float4*)(feat + ((size_t)blk << 12));
    float4 s0 = make_float4(0.f, 0.f, 0.f, 0.f);
    float4 sx = s0, sy = s0, sz2 = s0;

    #pragma unroll
    for (int it = 0; it < 4; it++) {
        int d = dgrp + it * 32;
        float4 f = f4[d * 8 + kq];
        float g0 = sgeo[0][d], g1 = sgeo[1][d], g2 = sgeo[2][d];
        s0.x += f.x;  s0.y += f.y;  s0.z += f.z;  s0.w += f.w;
        sx.x = fmaf(f.x, g0, sx.x);  sx.y = fmaf(f.y, g0, sx.y);
        sx.z = fmaf(f.z, g0, sx.z);  sx.w = fmaf(f.w, g0, sx.w);
        sy.x = fmaf(f.x, g1, sy.x);  sy.y = fmaf(f.y, g1, sy.y);
        sy.z = fmaf(f.z, g1, sy.z);  sy.w = fmaf(f.w, g1, sy.w);
        sz2.x = fmaf(f.x, g2, sz2.x);  sz2.y = fmaf(f.y, g2, sz2.y);
        sz2.z = fmaf(f.z, g2, sz2.z);  sz2.w = fmaf(f.w, g2, sz2.w);
    }

    smq[0][dgrp][kq] = s0;
    smq[1][dgrp][kq] = sx;
    smq[2][dgrp][kq] = sy;
    smq[3][dgrp][kq] = sz2;
    __syncthreads();

    if (t < 128) {
        int comp = t >> 5;
        int k = t & 31;
        const float* p = (const float*)&smq[comp][0][0];
        float s = 0.f;
        #pragma unroll
        for (int dg = 0; dg < 32; dg++) s += p[dg * 32 + k];
        red[comp][k] = s;
    }
    __syncthreads();

    if (t < 32) g_base[z][c][t] = ((const float4*)red)[t];
    __threadfence();
    __syncthreads();

    if (t == 0) {
        int old = atomicAdd(&g_cnt[z], 1);
        s_last = (old == NN - 1) ? 1 : 0;
    }
    __syncthreads();

    // ---- Middle (last block per z) / wait (others) ----
    if (s_last) {
        if (t == 0) {
            volatile int* wc = &g_w12cnt;
            while (*wc < 9) __nanosleep(64);
            int o3 = atomicAdd(&g_cnt3, 1);
            if (o3 == BZ - 1) { g_cnt3 = 0; g_w12cnt = 0; }   // all 4 passed
        }
        __syncthreads();
        __threadfence();

        // M[16][32]: gy-weighted reduce over c. Two slots per thread.
        for (int s = t; s < 512; s += 256) {
            int m = s >> 5;
            int k = s & 31;
            int b, y;
            if (m < 4)      { b = m;  y = -1; }
            else if (m < 7) { b = 0;  y = m - 4; }
            else            { int mm = m - 7; y = mm / 3; b = 1 + (mm - y * 3); }

            const float* base = (const float*)&g_base[z][0][0] + b * 32 + k;  // stride 128
            float acc = 0.f;
            if (y < 0) {
                #pragma unroll 16
                for (int cc = 0; cc < NN; cc++) acc += base[cc * 128];
            } else {
                const float* gy = &sgeo[y][0];
                #pragma unroll 16
                for (int cc = 0; cc < NN; cc++) acc = fmaf(base[cc * 128], gy[cc], acc);
            }
            sM[s] = acc;
        }
        __syncthreads();

        // U coefficients. Two slots per thread; W12 from global (L2-hot).
        const float* W12f = &g_W12g[0][0][0];
        for (int s = t; s < 512; s += 256) {
            float r = 0.f;
            if (s < 32) {
                int i = s;
                for (int yx = 0; yx < 9; yx++) {
                    const float* w = W12f + (yx * 32 + i) * 32;
                    const float* m2 = &sM[(7 + yx) * 32];
                    #pragma unroll
                    for (int k = 0; k < 32; k++) r = fmaf(w[k], m2[k], r);
                }
            } else if (s < 128) {
                int x = (s - 32) >> 5, i = s & 31;
                for (int y = 0; y < 3; y++) {
                    const float* w = W12f + ((y * 3 + x) * 32 + i) * 32;
                    const float* m2 = &sM[(4 + y) * 32];
                    #pragma unroll
                    for (int k = 0; k < 32; k++) r = fmaf(w[k], m2[k], r);
                }
            } else if (s < 224) {
                int y = (s - 128) >> 5, i = s & 31;
                for (int x = 0; x < 3; x++) {
                    const float* w = W12f + ((y * 3 + x) * 32 + i) * 32;
                    const float* m2 = &sM[(1 + x) * 32];
                    #pragma unroll
                    for (int k = 0; k < 32; k++) r = fmaf(w[k], m2[k], r);
                }
            } else {
                int m3 = s - 224;
                int yx = m3 >> 5, i = m3 & 31;
                const float* w = W12f + (yx * 32 + i) * 32;
                const float* m2 = &sM[0];
                #pragma unroll
                for (int k = 0; k < 32; k++) r = fmaf(w[k], m2[k], r);
            }
            g_U[z][s] = r;
        }
        __threadfence();
        __syncthreads();
        if (t == 0) atomicExch(&g_flag[z], 1);
    } else {
        if (t == 0) {
            volatile int* fl = &g_flag[z];
            while (*fl == 0) __nanosleep(64);
        }
        __syncthreads();
        __threadfence();
    }

    // ---- Load U, then release sync state for next replay ----
    sU[t] = g_U[z][t];
    sU[t + 256] = g_U[z][t + 256];
    __syncthreads();

    if (t == 0) {
        int o2 = atomicAdd(&g_cnt2[z], 1);
        if (o2 == NN - 1) {   // all 128 blocks of z have read g_U
            g_cnt[z] = 0; g_cnt2[z] = 0; g_flag[z] = 0;
        }
    }

    // ---- Expand: out[z, a=c, b, i] = V0[i] + sum_x gb_x * V1[x,i] ----
    float inv_n = 1.0f / load_scalar_f(n_norm_ptr);
    float ga0 = sgeo[0][c], ga1 = sgeo[1][c], ga2 = sgeo[2][c];

    if (t < 32) {
        int i = t;
        ((float*)V0q)[i] = inv_n *
            (sU[i] - (ga0 * sU[128 + i] + ga1 * sU[160 + i] + ga2 * sU[192 + i]));
    } else if (t < 128) {
        int x = (t - 32) >> 5, i = t & 31;
        ((float*)V1q)[x * 32 + i] = inv_n *
            (-sU[32 + x * 32 + i]
             + ga0 * sU[224 + (0 * 3 + x) * 32 + i]
             + ga1 * sU[224 + (1 * 3 + x) * 32 + i]
             + ga2 * sU[224 + (2 * 3 + x) * 32 + i]);
    }
    __syncthreads();

    int i4   = t & 7;
    int bgrp = t >> 3;   // 0..31

    float4 v0  = V0q[i4];
    float4 v10 = V1q[0][i4], v11 = V1q[1][i4], v12 = V1q[2][i4];

    float4* ob4 = (float4*)(out + ((size_t)blk << 12));
    #pragma unroll
    for (int it = 0; it < 4; it++) {
        int b = bgrp + it * 32;
        float gb0 = sgeo[0][b], gb1 = sgeo[1][b], gb2 = sgeo[2][b];
        float4 v;
        v.x = fmaf(gb2, v12.x, fmaf(gb1, v11.x, fmaf(gb0, v10.x, v0.x)));
        v.y = fmaf(gb2, v12.y, fmaf(gb1, v11.y, fmaf(gb0, v10.y, v0.y)));
        v.z = fmaf(gb2, v12.z, fmaf(gb1, v11.z, fmaf(gb0, v10.z, v0.z)));
        v.w = fmaf(gb2, v12.w, fmaf(gb1, v11.w, fmaf(gb0, v10.w, v0.w)));
        ob4[b * 8 + i4] = v;
    }
}

// ---------------------------------------------------------------------------
// kernel_launch
// Inputs: features f32[4,128,128,32], geometry f32[4,128,3],
//         W1 f32[3,32,32], W2 f32[3,32,32], n_norm scalar.
// Output: f32[4,128,128,32].
// ---------------------------------------------------------------------------
extern "C" void kernel_launch(void* const* d_in, const int* in_sizes, int n_in,
                              void* d_out, int out_size) {
    const float* feat = (const float*)d_in[0];
    const float* geo  = (const float*)d_in[1];
    const float* W1   = (const float*)d_in[2];
    const float* W2   = (const float*)d_in[3];
    const void*  nrm  = (n_in > 4) ? d_in[4] : nullptr;
    float* out = (float*)d_out;

    k_fused<<<BZ * NN + 9, 256>>>(feat, geo, W1, W2, nrm, out);
}

// round 9
// speedup vs baseline: 1.5304x; 1.5304x over previous
#include <cuda_runtime.h>
#include <cuda_bf16.h>
#include <cstdint>

// Problem shapes (fixed by setup_inputs): B=4, N=128, C_IN=C_OUT=32, X=3.
#define BZ 4
#define NN 128

// ---------------------------------------------------------------------------
// Scratch (no allocations allowed -> __device__ globals)
// ---------------------------------------------------------------------------
// Per-(z,c) BASE sums: row = 128 floats [b][k]: b=0: p0 = sum_d f;
// b=1..3: p1[x] = sum_d g[d,x]*f.
__device__ float4 g_base[BZ][NN][32];     // 256 KB
__device__ float  g_W12g[9][32][32];      // W12[yx][i][k] = sum_j W2[y,i,j]*W1[x,j,k]
__device__ float  g_U[BZ][512];           // U0[32] | U1[96] | U2[96] | U3[288]

// Robust scalar load: handles int32 or float32 encodings of n_norm.
__device__ __forceinline__ float load_scalar_f(const void* p) {
    int iv = *(const int*)p;
    int ex = (iv >> 23) & 0xFF;
    if (ex > 60 && ex < 200) return __int_as_float(iv);
    return (float)iv;
}

// ---------------------------------------------------------------------------
// K1: grid = BZ*NN + 9, 256 threads.
//   blocks [0..511]: per-(z,c) base sums. Feature loads issued BEFORE the
//     geo smem staging completes (independent), hiding the prologue latency.
//   blocks [512..520]: W12[yx] = W2[y] @ W1[x] -> g_W12g (no deps).
// ---------------------------------------------------------------------------
__global__ void __launch_bounds__(256) k_partial(const float* __restrict__ feat,
                                                 const float* __restrict__ geo,
                                                 const float* __restrict__ W1,
                                                 const float* __restrict__ W2) {
    int zc = blockIdx.x;
    int t = threadIdx.x;        // 256

    // ---- W12 producer blocks ----
    if (zc >= BZ * NN) {
        int yx = zc - BZ * NN;          // 0..8
        int y = yx / 3, x = yx - y * 3;
        #pragma unroll
        for (int r = 0; r < 4; r++) {
            int idx = t + r * 256;      // i*32 + k
            int i = idx >> 5, k = idx & 31;
            const float* w2r = W2 + (y * 32 + i) * 32;   // W2[y][i][j]
            const float* w1c = W1 + x * 1024 + k;        // W1[x][j][k]
            float acc = 0.f;
            #pragma unroll
            for (int j = 0; j < 32; j++) acc = fmaf(w2r[j], w1c[j * 32], acc);
            g_W12g[yx][i][k] = acc;
        }
        return;
    }

    int z = zc >> 7;
    int kq   = t & 7;           // float4 index within the 32-float k-row
    int dgrp = t >> 3;          // 0..31

    __shared__ float  sgeo[384];       // geo[z] flat: [d*3 + comp]
    __shared__ float4 smq[4][32][8];   // [comp][dgrp][kq], 16 KB
    __shared__ float  red[4][32];

    // Issue geo loads (registers) — then feature loads — then store+sync.
    float gv0 = geo[z * 384 + t];
    float gv1 = (t < 128) ? geo[z * 384 + 256 + t] : 0.f;

    const float4* f4 = (const float4*)(feat + ((size_t)zc << 12));
    float4 f0 = f4[(dgrp +  0) * 8 + kq];
    float4 f1 = f4[(dgrp + 32) * 8 + kq];
    float4 f2 = f4[(dgrp + 64) * 8 + kq];
    float4 f3 = f4[(dgrp + 96) * 8 + kq];

    sgeo[t] = gv0;
    if (t < 128) sgeo[256 + t] = gv1;
    __syncthreads();

    float4 s0 = make_float4(0.f, 0.f, 0.f, 0.f);
    float4 sx = s0, sy = s0, sz2 = s0;

    float4 fv[4] = {f0, f1, f2, f3};
    #pragma unroll
    for (int it = 0; it < 4; it++) {
        int d = dgrp + it * 32;
        float4 f = fv[it];
        float g0 = sgeo[d * 3 + 0], g1 = sgeo[d * 3 + 1], g2 = sgeo[d * 3 + 2];
        s0.x += f.x;  s0.y += f.y;  s0.z += f.z;  s0.w += f.w;
        sx.x = fmaf(f.x, g0, sx.x);  sx.y = fmaf(f.y, g0, sx.y);
        sx.z = fmaf(f.z, g0, sx.z);  sx.w = fmaf(f.w, g0, sx.w);
        sy.x = fmaf(f.x, g1, sy.x);  sy.y = fmaf(f.y, g1, sy.y);
        sy.z = fmaf(f.z, g1, sy.z);  sy.w = fmaf(f.w, g1, sy.w);
        sz2.x = fmaf(f.x, g2, sz2.x);  sz2.y = fmaf(f.y, g2, sz2.y);
        sz2.z = fmaf(f.z, g2, sz2.z);  sz2.w = fmaf(f.w, g2, sz2.w);
    }

    smq[0][dgrp][kq] = s0;
    smq[1][dgrp][kq] = sx;
    smq[2][dgrp][kq] = sy;
    smq[3][dgrp][kq] = sz2;
    __syncthreads();

    // Reduce over 32 dgrps: threads t<128 -> (comp = t>>5, k = t&31).
    if (t < 128) {
        int comp = t >> 5;
        int k = t & 31;
        const float* p = (const float*)&smq[comp][0][0];  // 1024 floats
        float s = 0.f;
        #pragma unroll
        for (int dg = 0; dg < 32; dg++) s += p[dg * 32 + k];
        red[comp][k] = s;
    }
    __syncthreads();

    if (t < 32) {
        int c = zc & (NN - 1);
        g_base[z][c][t] = ((const float4*)red)[t];
    }
}

// ---------------------------------------------------------------------------
// K2: per-z middle. grid = B, 512 threads.
//   (1) M[16][32]: gy-weighted reduce over c from g_base (one slot/thread)
//   (2) U coefficients, W12 read from g_W12g (L2-hot, written by K1)
//   M rows: m=0: p0; m=1..3: p1[x]; m=4..6: gy[y]*p0; m=7..15: gy[y]*p1[x]
// ---------------------------------------------------------------------------
__global__ void __launch_bounds__(512, 1) k_middle(const float* __restrict__ geo) {
    int z = blockIdx.x;
    int t = threadIdx.x;  // 512

    __shared__ float sM[512];        // 16 moment rows of 32
    __shared__ float sgeo[3][NN];

    if (t < NN * 3) {
        int c = t / 3, comp = t - c * 3;
        sgeo[comp][c] = geo[z * NN * 3 + t];
    }
    __syncthreads();

    // (1) gy-weighted reduce over c. One (m,k) slot per thread.
    {
        int m = t >> 5;
        int k = t & 31;
        int b, y;
        if (m < 4)      { b = m;  y = -1; }
        else if (m < 7) { b = 0;  y = m - 4; }
        else            { int mm = m - 7; y = mm / 3; b = 1 + (mm - y * 3); }

        const float* base = (const float*)&g_base[z][0][0] + b * 32 + k;  // stride 128
        float s = 0.f;
        if (y < 0) {
            #pragma unroll 16
            for (int c = 0; c < NN; c++) s += base[c * 128];
        } else {
            const float* gy = &sgeo[y][0];
            #pragma unroll 16
            for (int c = 0; c < NN; c++) s = fmaf(base[c * 128], gy[c], s);
        }
        sM[t] = s;
    }
    __syncthreads();

    // (2) U from sM + g_W12g. One output per thread.
    const float* W12f = &g_W12g[0][0][0];
    float r = 0.f;
    if (t < 32) {
        int i = t;
        for (int yx = 0; yx < 9; yx++) {
            const float* w = W12f + (yx * 32 + i) * 32;
            const float* m2 = &sM[(7 + yx) * 32];
            #pragma unroll
            for (int k = 0; k < 32; k++) r = fmaf(__ldg(w + k), m2[k], r);
        }
    } else if (t < 128) {
        int x = (t - 32) >> 5, i = t & 31;
        for (int y = 0; y < 3; y++) {
            const float* w = W12f + ((y * 3 + x) * 32 + i) * 32;
            const float* m2 = &sM[(4 + y) * 32];
            #pragma unroll
            for (int k = 0; k < 32; k++) r = fmaf(__ldg(w + k), m2[k], r);
        }
    } else if (t < 224) {
        int y = (t - 128) >> 5, i = t & 31;
        for (int x = 0; x < 3; x++) {
            const float* w = W12f + ((y * 3 + x) * 32 + i) * 32;
            const float* m2 = &sM[(1 + x) * 32];
            #pragma unroll
            for (int k = 0; k < 32; k++) r = fmaf(__ldg(w + k), m2[k], r);
        }
    } else {
        int m3 = t - 224;
        int yx = m3 >> 5, i = m3 & 31;
        const float* w = W12f + (yx * 32 + i) * 32;
        const float* m2 = &sM[0];
        #pragma unroll
        for (int k = 0; k < 32; k++) r = fmaf(__ldg(w + k), m2[k], r);
    }
    g_U[z][t] = r;
}

// ---------------------------------------------------------------------------
// K3: output expansion. grid = B*N (one block per (z,a)), 256 threads.
// out[z,a,b,i] = V0[i] + sum_x gb_x * V1[x,i]   (V pre-scaled by 1/n)
// ---------------------------------------------------------------------------
__global__ void __launch_bounds__(256) k_expand(const float* __restrict__ geo,
                                                float* __restrict__ out,
                                                const void* __restrict__ n_norm_ptr) {
    int za = blockIdx.x;
    int z = za >> 7;
    int a = za & (NN - 1);
    int t = threadIdx.x;  // 256

    __shared__ float  sU[512];
    __shared__ float  sg[NN * 3];
    __shared__ float4 V0q[8];        // V0[32]
    __shared__ float4 V1q[3][8];     // V1[3][32]

    // Issue all independent loads up front.
    float u0 = g_U[z][t];
    float u1 = g_U[z][t + 256];
    float gv0 = geo[z * 384 + t];
    float gv1 = (t < 128) ? geo[z * 384 + 256 + t] : 0.f;

    sU[t] = u0;
    sU[t + 256] = u1;
    sg[t] = gv0;
    if (t < 128) sg[256 + t] = gv1;
    __syncthreads();

    float inv_n = 1.0f / load_scalar_f(n_norm_ptr);
    float ga0 = sg[a * 3 + 0], ga1 = sg[a * 3 + 1], ga2 = sg[a * 3 + 2];

    if (t < 32) {
        int i = t;
        ((float*)V0q)[i] = inv_n *
            (sU[i] - (ga0 * sU[128 + i] + ga1 * sU[160 + i] + ga2 * sU[192 + i]));
    } else if (t < 128) {
        int x = (t - 32) >> 5, i = t & 31;
        ((float*)V1q)[x * 32 + i] = inv_n *
            (-sU[32 + x * 32 + i]
             + ga0 * sU[224 + (0 * 3 + x) * 32 + i]
             + ga1 * sU[224 + (1 * 3 + x) * 32 + i]
             + ga2 * sU[224 + (2 * 3 + x) * 32 + i]);
    }
    __syncthreads();

    int i4   = t & 7;    // which float4 of the 32-float output row
    int bgrp = t >> 3;   // 0..31

    float4 v0  = V0q[i4];
    float4 v10 = V1q[0][i4], v11 = V1q[1][i4], v12 = V1q[2][i4];

    float4* ob4 = (float4*)(out + ((size_t)za << 12));
    #pragma unroll
    for (int it = 0; it < 4; it++) {
        int b = bgrp + it * 32;
        float gb0 = sg[b * 3 + 0], gb1 = sg[b * 3 + 1], gb2 = sg[b * 3 + 2];
        float4 v;
        v.x = fmaf(gb2, v12.x, fmaf(gb1, v11.x, fmaf(gb0, v10.x, v0.x)));
        v.y = fmaf(gb2, v12.y, fmaf(gb1, v11.y, fmaf(gb0, v10.y, v0.y)));
        v.z = fmaf(gb2, v12.z, fmaf(gb1, v11.z, fmaf(gb0, v10.z, v0.z)));
        v.w = fmaf(gb2, v12.w, fmaf(gb1, v11.w, fmaf(gb0, v10.w, v0.w)));
        ob4[b * 8 + i4] = v;
    }
}

// ---------------------------------------------------------------------------
// kernel_launch
// Inputs: features f32[4,128,128,32], geometry f32[4,128,3],
//         W1 f32[3,32,32], W2 f32[3,32,32], n_norm scalar.
// Output: f32[4,128,128,32].
// ---------------------------------------------------------------------------
extern "C" void kernel_launch(void* const* d_in, const int* in_sizes, int n_in,
                              void* d_out, int out_size) {
    const float* feat = (const float*)d_in[0];
    const float* geo  = (const float*)d_in[1];
    const float* W1   = (const float*)d_in[2];
    const float* W2   = (const float*)d_in[3];
    const void*  nrm  = (n_in > 4) ? d_in[4] : nullptr;
    float* out = (float*)d_out;

    k_partial<<<BZ * NN + 9, 256>>>(feat, geo, W1, W2);
    k_middle<<<BZ, 512>>>(geo);
    k_expand<<<BZ * NN, 256>>>(geo, out, nrm);
}

// round 10
// speedup vs baseline: 2.6435x; 1.7273x over previous
#include <cuda_runtime.h>
#include <cuda_bf16.h>
#include <cstdint>

// Problem shapes (fixed by setup_inputs): B=4, N=128, C_IN=C_OUT=32, X=3.
#define BZ 4
#define NN 128

// ---------------------------------------------------------------------------
// Scratch (no allocations allowed -> __device__ globals)
// ---------------------------------------------------------------------------
// Per-(z,c) BASE sums: row = 128 floats [b][k]: b=0: p0 = sum_d f;
// b=1..3: p1[x] = sum_d g[d,x]*f.
__device__ float4 g_base[BZ][NN][32];     // 256 KB
__device__ float  g_W12g[9 * 32 * 32];    // W12[yx][i][k] = sum_j W2[y,i,j]*W1[x,j,k]
__device__ float  g_U[BZ][512];           // U0[32] | U1[96] | U2[96] | U3[288]

// Robust scalar load: handles int32 or float32 encodings of n_norm.
__device__ __forceinline__ float load_scalar_f(const void* p) {
    int iv = *(const int*)p;
    int ex = (iv >> 23) & 0xFF;
    if (ex > 60 && ex < 200) return __int_as_float(iv);
    return (float)iv;
}

// ---------------------------------------------------------------------------
// K1: grid = BZ*NN + 9, 256 threads.
//   blocks [0..511]: per-(z,c) base sums (r7 loop shape, unchanged).
//   blocks [512..520]: W12[yx] = W2[y] @ W1[x] -> g_W12g (no deps, riders).
// ---------------------------------------------------------------------------
__global__ void __launch_bounds__(256) k_partial(const float* __restrict__ feat,
                                                 const float* __restrict__ geo,
                                                 const float* __restrict__ W1,
                                                 const float* __restrict__ W2) {
    int zc = blockIdx.x;
    int t = threadIdx.x;        // 256

    // ---- W12 rider blocks ----
    if (zc >= BZ * NN) {
        int yx = zc - BZ * NN;          // 0..8
        int y = yx / 3, x = yx - y * 3;
        #pragma unroll
        for (int r = 0; r < 4; r++) {
            int idx = t + r * 256;      // i*32 + k
            int i = idx >> 5, k = idx & 31;
            const float* w2r = W2 + (y * 32 + i) * 32;   // W2[y][i][j]
            const float* w1c = W1 + x * 1024 + k;        // W1[x][j][k]
            float acc = 0.f;
            #pragma unroll
            for (int j = 0; j < 32; j++) acc = fmaf(w2r[j], w1c[j * 32], acc);
            g_W12g[yx * 1024 + i * 32 + k] = acc;
        }
        return;
    }

    int z = zc >> 7;
    int kq   = t & 7;           // which float4 within the 32-float k-row
    int dgrp = t >> 3;          // 0..31

    __shared__ float  sgeo[3][NN];     // geo[z] transposed: [comp][d]
    __shared__ float4 smq[4][32][8];   // [comp][dgrp][kq], 16 KB
    __shared__ float  red[4][32];      // reduced sums [comp][k]

    if (t < NN * 3) {
        int d = t / 3, comp = t - d * 3;
        sgeo[comp][d] = geo[z * NN * 3 + t];
    }
    if (t + 256 < NN * 3) {
        int idx = t + 256;
        int d = idx / 3, comp = idx - d * 3;
        sgeo[comp][d] = geo[z * NN * 3 + idx];
    }
    __syncthreads();

    const float4* f4 = (const float4*)(feat + ((size_t)zc << 12));
    float4 s0 = make_float4(0.f, 0.f, 0.f, 0.f);
    float4 sx = s0, sy = s0, sz2 = s0;

    #pragma unroll
    for (int it = 0; it < 4; it++) {
        int d = dgrp + it * 32;
        float4 f = f4[d * 8 + kq];
        float g0 = sgeo[0][d], g1 = sgeo[1][d], g2 = sgeo[2][d];
        s0.x += f.x;  s0.y += f.y;  s0.z += f.z;  s0.w += f.w;
        sx.x = fmaf(f.x, g0, sx.x);  sx.y = fmaf(f.y, g0, sx.y);
        sx.z = fmaf(f.z, g0, sx.z);  sx.w = fmaf(f.w, g0, sx.w);
        sy.x = fmaf(f.x, g1, sy.x);  sy.y = fmaf(f.y, g1, sy.y);
        sy.z = fmaf(f.z, g1, sy.z);  sy.w = fmaf(f.w, g1, sy.w);
        sz2.x = fmaf(f.x, g2, sz2.x);  sz2.y = fmaf(f.y, g2, sz2.y);
        sz2.z = fmaf(f.z, g2, sz2.z);  sz2.w = fmaf(f.w, g2, sz2.w);
    }

    smq[0][dgrp][kq] = s0;
    smq[1][dgrp][kq] = sx;
    smq[2][dgrp][kq] = sy;
    smq[3][dgrp][kq] = sz2;
    __syncthreads();

    // Reduce over 32 dgrps: threads t<128 -> (comp = t>>5, k = t&31).
    if (t < 128) {
        int comp = t >> 5;
        int k = t & 31;
        const float* p = (const float*)&smq[comp][0][0];  // 1024 floats
        float s = 0.f;
        #pragma unroll
        for (int dg = 0; dg < 32; dg++) s += p[dg * 32 + k];
        red[comp][k] = s;
    }
    __syncthreads();

    // Write the 128-float base row as 32 float4s (coalesced 512B).
    if (t < 32) {
        int c = zc & (NN - 1);
        g_base[z][c][t] = ((const float4*)red)[t];
    }
}

// ---------------------------------------------------------------------------
// K2: per-z middle. grid = B, 512 threads.
//   (0) bulk-copy precomputed W12 from g_W12g into shared (L2-hot, coalesced)
//   (1) M[16][32]: gy-weighted reduce over c from g_base
//   (2) U coefficients from shared
//   M rows: m=0: p0; m=1..3: p1[x]; m=4..6: gy[y]*p0; m=7..15: gy[y]*p1[x]
// ---------------------------------------------------------------------------
__global__ void __launch_bounds__(512, 1) k_middle(const float* __restrict__ geo) {
    int z = blockIdx.x;
    int t = threadIdx.x;  // 512

    __shared__ float sW12[9 * 32 * 32];  // 36 KB: [yx][i][k]
    __shared__ float sM[16][32];         // 2 KB
    __shared__ float sgeo[3][NN];        // 1.5 KB

    if (t < NN * 3) {
        int c = t / 3, comp = t - c * 3;
        sgeo[comp][c] = geo[z * NN * 3 + t];
    }

    // (0) copy W12: 2304 float4 across 512 threads (coalesced, independent).
    {
        float4* s4 = (float4*)sW12;
        const float4* g4 = (const float4*)g_W12g;
        #pragma unroll
        for (int r = 0; r < 4; r++) s4[t + r * 512] = g4[t + r * 512];
        if (t < 2304 - 2048) s4[t + 2048] = g4[t + 2048];
    }

    // (1) gy-weighted reduce over c. One (m,k) slot per thread. Needs sgeo.
    __syncthreads();
    {
        int m = t >> 5;
        int k = t & 31;
        int b, y;
        if (m < 4)      { b = m;  y = -1; }
        else if (m < 7) { b = 0;  y = m - 4; }
        else            { int mm = m - 7; y = mm / 3; b = 1 + (mm - y * 3); }

        const float* base = (const float*)&g_base[z][0][0] + b * 32 + k;  // stride 128
        float s = 0.f;
        if (y < 0) {
            #pragma unroll 16
            for (int c = 0; c < NN; c++) s += base[c * 128];
        } else {
            const float* gy = &sgeo[y][0];
            #pragma unroll 16
            for (int c = 0; c < NN; c++) s = fmaf(base[c * 128], gy[c], s);
        }
        (&sM[0][0])[t] = s;
    }
    __syncthreads();

    // (2) U from shared. One output per thread.
    float r = 0.f;
    if (t < 32) {
        int i = t;
        for (int yx = 0; yx < 9; yx++) {
            const float* w = &sW12[(yx * 32 + i) * 32];
            const float* m = &sM[7 + yx][0];
            #pragma unroll
            for (int k = 0; k < 32; k++) r = fmaf(w[k], m[k], r);
        }
    } else if (t < 128) {
        int x = (t - 32) >> 5, i = t & 31;
        for (int y = 0; y < 3; y++) {
            const float* w = &sW12[((y * 3 + x) * 32 + i) * 32];
            const float* m = &sM[4 + y][0];
            #pragma unroll
            for (int k = 0; k < 32; k++) r = fmaf(w[k], m[k], r);
        }
    } else if (t < 224) {
        int y = (t - 128) >> 5, i = t & 31;
        for (int x = 0; x < 3; x++) {
            const float* w = &sW12[((y * 3 + x) * 32 + i) * 32];
            const float* m = &sM[1 + x][0];
            #pragma unroll
            for (int k = 0; k < 32; k++) r = fmaf(w[k], m[k], r);
        }
    } else {
        int m3 = t - 224;
        int yx = m3 >> 5, i = m3 & 31;
        const float* w = &sW12[(yx * 32 + i) * 32];
        const float* m = &sM[0][0];
        #pragma unroll
        for (int k = 0; k < 32; k++) r = fmaf(w[k], m[k], r);
    }
    g_U[z][t] = r;
}

// ---------------------------------------------------------------------------
// K3: output expansion. grid = B*N (one block per (z,a)), 256 threads.
// out[z,a,b,i] = V0[i] + sum_x gb_x * V1[x,i]   (V pre-scaled by 1/n)
// ---------------------------------------------------------------------------
__global__ void __launch_bounds__(256) k_expand(const float* __restrict__ geo,
                                                float* __restrict__ out,
                                                const void* __restrict__ n_norm_ptr) {
    int za = blockIdx.x;
    int z = za >> 7;
    int a = za & (NN - 1);
    int t = threadIdx.x;  // 256

    __shared__ float  sU[512];
    __shared__ float  sg[NN * 3];
    __shared__ float4 V0q[8];        // V0[32]
    __shared__ float4 V1q[3][8];     // V1[3][32]

    sU[t] = g_U[z][t];
    sU[t + 256] = g_U[z][t + 256];
    for (int idx = t; idx < NN * 3; idx += 256) sg[idx] = geo[z * NN * 3 + idx];
    __syncthreads();

    float inv_n = 1.0f / load_scalar_f(n_norm_ptr);
    float ga0 = sg[a * 3 + 0], ga1 = sg[a * 3 + 1], ga2 = sg[a * 3 + 2];

    if (t < 32) {
        int i = t;
        ((float*)V0q)[i] = inv_n *
            (sU[i] - (ga0 * sU[128 + i] + ga1 * sU[160 + i] + ga2 * sU[192 + i]));
    } else if (t < 128) {
        int x = (t - 32) >> 5, i = t & 31;
        ((float*)V1q)[x * 32 + i] = inv_n *
            (-sU[32 + x * 32 + i]
             + ga0 * sU[224 + (0 * 3 + x) * 32 + i]
             + ga1 * sU[224 + (1 * 3 + x) * 32 + i]
             + ga2 * sU[224 + (2 * 3 + x) * 32 + i]);
    }
    __syncthreads();

    int i4   = t & 7;    // which float4 of the 32-float output row
    int bgrp = t >> 3;   // 0..31

    float4 v0  = V0q[i4];
    float4 v10 = V1q[0][i4], v11 = V1q[1][i4], v12 = V1q[2][i4];

    float4* ob4 = (float4*)(out + ((size_t)za << 12));
    #pragma unroll
    for (int it = 0; it < 4; it++) {
        int b = bgrp + it * 32;
        float gb0 = sg[b * 3 + 0], gb1 = sg[b * 3 + 1], gb2 = sg[b * 3 + 2];
        float4 v;
        v.x = fmaf(gb2, v12.x, fmaf(gb1, v11.x, fmaf(gb0, v10.x, v0.x)));
        v.y = fmaf(gb2, v12.y, fmaf(gb1, v11.y, fmaf(gb0, v10.y, v0.y)));
        v.z = fmaf(gb2, v12.z, fmaf(gb1, v11.z, fmaf(gb0, v10.z, v0.z)));
        v.w = fmaf(gb2, v12.w, fmaf(gb1, v11.w, fmaf(gb0, v10.w, v0.w)));
        ob4[b * 8 + i4] = v;
    }
}

// ---------------------------------------------------------------------------
// kernel_launch
// Inputs: features f32[4,128,128,32], geometry f32[4,128,3],
//         W1 f32[3,32,32], W2 f32[3,32,32], n_norm scalar.
// Output: f32[4,128,128,32].
// ---------------------------------------------------------------------------
extern "C" void kernel_launch(void* const* d_in, const int* in_sizes, int n_in,
                              void* d_out, int out_size) {
    const float* feat = (const float*)d_in[0];
    const float* geo  = (const float*)d_in[1];
    const float* W1   = (const float*)d_in[2];
    const float* W2   = (const float*)d_in[3];
    const void*  nrm  = (n_in > 4) ? d_in[4] : nullptr;
    float* out = (float*)d_out;

    k_partial<<<BZ * NN + 9, 256>>>(feat, geo, W1, W2);
    k_middle<<<BZ, 512>>>(geo);
    k_expand<<<BZ * NN, 256>>>(geo, out, nrm);
}

// round 11
// speedup vs baseline: 2.8499x; 1.0781x over previous
#include <cuda_runtime.h>
#include <cuda_bf16.h>
#include <cstdint>

// Problem shapes (fixed by setup_inputs): B=4, N=128, C_IN=C_OUT=32, X=3.
#define BZ 4
#define NN 128

// ---------------------------------------------------------------------------
// Scratch (no allocations allowed -> __device__ globals)
// ---------------------------------------------------------------------------
// Per-(z,c) BASE sums: row = 128 floats [b][k]: b=0: p0 = sum_d f;
// b=1..3: p1[x] = sum_d g[d,x]*f.
__device__ float4 g_base[BZ][NN][32];     // 256 KB
__device__ float  g_W12g[9 * 32 * 32];    // W12[yx][i][k] = sum_j W2[y,i,j]*W1[x,j,k]
__device__ float  g_U[BZ][512];           // U0[32] | U1[96] | U2[96] | U3[288]

// Robust scalar load: handles int32 or float32 encodings of n_norm.
__device__ __forceinline__ float load_scalar_f(const void* p) {
    int iv = *(const int*)p;
    int ex = (iv >> 23) & 0xFF;
    if (ex > 60 && ex < 200) return __int_as_float(iv);
    return (float)iv;
}

// ---------------------------------------------------------------------------
// K1: grid = BZ*NN + 9, 256 threads, regs capped (rider path must not inflate
// the main path's allocation — r10 evidence: riders pushed 37->64 regs and
// k_partial 5.76->8.06us).
//   blocks [0..511]: per-(z,c) base sums (r7 loop shape, unchanged).
//   blocks [512..520]: W12[yx] = W2[y] @ W1[x] via smem staging (reg-light).
// ---------------------------------------------------------------------------
__global__ void __launch_bounds__(256, 6) k_partial(const float* __restrict__ feat,
                                                    const float* __restrict__ geo,
                                                    const float* __restrict__ W1,
                                                    const float* __restrict__ W2) {
    int zc = blockIdx.x;
    int t = threadIdx.x;        // 256

    // ---- W12 rider blocks: stage weights in smem, then LDS-fed FMA chains ----
    if (zc >= BZ * NN) {
        __shared__ float sw1[1024];   // W1[x][j][k]
        __shared__ float sw2[1024];   // W2[y][i][j]
        int yx = zc - BZ * NN;        // 0..8
        int y = yx / 3, x = yx - y * 3;
        #pragma unroll
        for (int r = 0; r < 4; r++) {
            sw2[t + r * 256] = W2[y * 1024 + t + r * 256];
            sw1[t + r * 256] = W1[x * 1024 + t + r * 256];
        }
        __syncthreads();
        #pragma unroll
        for (int r = 0; r < 4; r++) {
            int idx = t + r * 256;    // i*32 + k
            int i = idx >> 5, k = idx & 31;
            float acc = 0.f;
            #pragma unroll
            for (int j = 0; j < 32; j++) acc = fmaf(sw2[i * 32 + j], sw1[j * 32 + k], acc);
            g_W12g[yx * 1024 + idx] = acc;
        }
        return;
    }

    int z = zc >> 7;
    int kq   = t & 7;           // which float4 within the 32-float k-row
    int dgrp = t >> 3;          // 0..31

    __shared__ float  sgeo[3][NN];     // geo[z] transposed: [comp][d]
    __shared__ float4 smq[4][32][8];   // [comp][dgrp][kq], 16 KB
    __shared__ float  red[4][32];      // reduced sums [comp][k]

    if (t < NN * 3) {
        int d = t / 3, comp = t - d * 3;
        sgeo[comp][d] = geo[z * NN * 3 + t];
    }
    if (t + 256 < NN * 3) {
        int idx = t + 256;
        int d = idx / 3, comp = idx - d * 3;
        sgeo[comp][d] = geo[z * NN * 3 + idx];
    }
    __syncthreads();

    const float4* f4 = (const float4*)(feat + ((size_t)zc << 12));
    float4 s0 = make_float4(0.f, 0.f, 0.f, 0.f);
    float4 sx = s0, sy = s0, sz2 = s0;

    #pragma unroll
    for (int it = 0; it < 4; it++) {
        int d = dgrp + it * 32;
        float4 f = f4[d * 8 + kq];
        float g0 = sgeo[0][d], g1 = sgeo[1][d], g2 = sgeo[2][d];
        s0.x += f.x;  s0.y += f.y;  s0.z += f.z;  s0.w += f.w;
        sx.x = fmaf(f.x, g0, sx.x);  sx.y = fmaf(f.y, g0, sx.y);
        sx.z = fmaf(f.z, g0, sx.z);  sx.w = fmaf(f.w, g0, sx.w);
        sy.x = fmaf(f.x, g1, sy.x);  sy.y = fmaf(f.y, g1, sy.y);
        sy.z = fmaf(f.z, g1, sy.z);  sy.w = fmaf(f.w, g1, sy.w);
        sz2.x = fmaf(f.x, g2, sz2.x);  sz2.y = fmaf(f.y, g2, sz2.y);
        sz2.z = fmaf(f.z, g2, sz2.z);  sz2.w = fmaf(f.w, g2, sz2.w);
    }

    smq[0][dgrp][kq] = s0;
    smq[1][dgrp][kq] = sx;
    smq[2][dgrp][kq] = sy;
    smq[3][dgrp][kq] = sz2;
    __syncthreads();

    // Reduce over 32 dgrps: threads t<128 -> (comp = t>>5, k = t&31).
    if (t < 128) {
        int comp = t >> 5;
        int k = t & 31;
        const float* p = (const float*)&smq[comp][0][0];  // 1024 floats
        float s = 0.f;
        #pragma unroll
        for (int dg = 0; dg < 32; dg++) s += p[dg * 32 + k];
        red[comp][k] = s;
    }
    __syncthreads();

    // Write the 128-float base row as 32 float4s (coalesced 512B).
    if (t < 32) {
        int c = zc & (NN - 1);
        g_base[z][c][t] = ((const float4*)red)[t];
    }
}

// ---------------------------------------------------------------------------
// K2: per-z middle. grid = B, 512 threads.
//   (0) bulk-copy precomputed W12 from g_W12g into shared (L2-hot, coalesced)
//   (1) M[16][32]: gy-weighted reduce over c from g_base
//   (2) U coefficients from shared
//   M rows: m=0: p0; m=1..3: p1[x]; m=4..6: gy[y]*p0; m=7..15: gy[y]*p1[x]
// ---------------------------------------------------------------------------
__global__ void __launch_bounds__(512, 1) k_middle(const float* __restrict__ geo) {
    int z = blockIdx.x;
    int t = threadIdx.x;  // 512

    __shared__ float sW12[9 * 32 * 32];  // 36 KB: [yx][i][k]
    __shared__ float sM[16][32];         // 2 KB
    __shared__ float sgeo[3][NN];        // 1.5 KB

    if (t < NN * 3) {
        int c = t / 3, comp = t - c * 3;
        sgeo[comp][c] = geo[z * NN * 3 + t];
    }

    // (0) copy W12: 2304 float4 across 512 threads (coalesced, independent).
    {
        float4* s4 = (float4*)sW12;
        const float4* g4 = (const float4*)g_W12g;
        #pragma unroll
        for (int r = 0; r < 4; r++) s4[t + r * 512] = g4[t + r * 512];
        if (t < 2304 - 2048) s4[t + 2048] = g4[t + 2048];
    }

    // (1) gy-weighted reduce over c. One (m,k) slot per thread. Needs sgeo.
    __syncthreads();
    {
        int m = t >> 5;
        int k = t & 31;
        int b, y;
        if (m < 4)      { b = m;  y = -1; }
        else if (m < 7) { b = 0;  y = m - 4; }
        else            { int mm = m - 7; y = mm / 3; b = 1 + (mm - y * 3); }

        const float* base = (const float*)&g_base[z][0][0] + b * 32 + k;  // stride 128
        float s = 0.f;
        if (y < 0) {
            #pragma unroll 16
            for (int c = 0; c < NN; c++) s += base[c * 128];
        } else {
            const float* gy = &sgeo[y][0];
            #pragma unroll 16
            for (int c = 0; c < NN; c++) s = fmaf(base[c * 128], gy[c], s);
        }
        (&sM[0][0])[t] = s;
    }
    __syncthreads();

    // (2) U from shared. One output per thread.
    float r = 0.f;
    if (t < 32) {
        int i = t;
        for (int yx = 0; yx < 9; yx++) {
            const float* w = &sW12[(yx * 32 + i) * 32];
            const float* m = &sM[7 + yx][0];
            #pragma unroll
            for (int k = 0; k < 32; k++) r = fmaf(w[k], m[k], r);
        }
    } else if (t < 128) {
        int x = (t - 32) >> 5, i = t & 31;
        for (int y = 0; y < 3; y++) {
            const float* w = &sW12[((y * 3 + x) * 32 + i) * 32];
            const float* m = &sM[4 + y][0];
            #pragma unroll
            for (int k = 0; k < 32; k++) r = fmaf(w[k], m[k], r);
        }
    } else if (t < 224) {
        int y = (t - 128) >> 5, i = t & 31;
        for (int x = 0; x < 3; x++) {
            const float* w = &sW12[((y * 3 + x) * 32 + i) * 32];
            const float* m = &sM[1 + x][0];
            #pragma unroll
            for (int k = 0; k < 32; k++) r = fmaf(w[k], m[k], r);
        }
    } else {
        int m3 = t - 224;
        int yx = m3 >> 5, i = m3 & 31;
        const float* w = &sW12[(yx * 32 + i) * 32];
        const float* m = &sM[0][0];
        #pragma unroll
        for (int k = 0; k < 32; k++) r = fmaf(w[k], m[k], r);
    }
    g_U[z][t] = r;
}

// ---------------------------------------------------------------------------
// K3: output expansion. grid = B*N (one block per (z,a)), 256 threads.
// out[z,a,b,i] = V0[i] + sum_x gb_x * V1[x,i]   (V pre-scaled by 1/n)
// ---------------------------------------------------------------------------
__global__ void __launch_bounds__(256) k_expand(const float* __restrict__ geo,
                                                float* __restrict__ out,
                                                const void* __restrict__ n_norm_ptr) {
    int za = blockIdx.x;
    int z = za >> 7;
    int a = za & (NN - 1);
    int t = threadIdx.x;  // 256

    __shared__ float  sU[512];
    __shared__ float  sg[NN * 3];
    __shared__ float4 V0q[8];        // V0[32]
    __shared__ float4 V1q[3][8];     // V1[3][32]

    sU[t] = g_U[z][t];
    sU[t + 256] = g_U[z][t + 256];
    for (int idx = t; idx < NN * 3; idx += 256) sg[idx] = geo[z * NN * 3 + idx];
    __syncthreads();

    float inv_n = 1.0f / load_scalar_f(n_norm_ptr);
    float ga0 = sg[a * 3 + 0], ga1 = sg[a * 3 + 1], ga2 = sg[a * 3 + 2];

    if (t < 32) {
        int i = t;
        ((float*)V0q)[i] = inv_n *
            (sU[i] - (ga0 * sU[128 + i] + ga1 * sU[160 + i] + ga2 * sU[192 + i]));
    } else if (t < 128) {
        int x = (t - 32) >> 5, i = t & 31;
        ((float*)V1q)[x * 32 + i] = inv_n *
            (-sU[32 + x * 32 + i]
             + ga0 * sU[224 + (0 * 3 + x) * 32 + i]
             + ga1 * sU[224 + (1 * 3 + x) * 32 + i]
             + ga2 * sU[224 + (2 * 3 + x) * 32 + i]);
    }
    __syncthreads();

    int i4   = t & 7;    // which float4 of the 32-float output row
    int bgrp = t >> 3;   // 0..31

    float4 v0  = V0q[i4];
    float4 v10 = V1q[0][i4], v11 = V1q[1][i4], v12 = V1q[2][i4];

    float4* ob4 = (float4*)(out + ((size_t)za << 12));
    #pragma unroll
    for (int it = 0; it < 4; it++) {
        int b = bgrp + it * 32;
        float gb0 = sg[b * 3 + 0], gb1 = sg[b * 3 + 1], gb2 = sg[b * 3 + 2];
        float4 v;
        v.x = fmaf(gb2, v12.x, fmaf(gb1, v11.x, fmaf(gb0, v10.x, v0.x)));
        v.y = fmaf(gb2, v12.y, fmaf(gb1, v11.y, fmaf(gb0, v10.y, v0.y)));
        v.z = fmaf(gb2, v12.z, fmaf(gb1, v11.z, fmaf(gb0, v10.z, v0.z)));
        v.w = fmaf(gb2, v12.w, fmaf(gb1, v11.w, fmaf(gb0, v10.w, v0.w)));
        ob4[b * 8 + i4] = v;
    }
}

// ---------------------------------------------------------------------------
// kernel_launch
// Inputs: features f32[4,128,128,32], geometry f32[4,128,3],
//         W1 f32[3,32,32], W2 f32[3,32,32], n_norm scalar.
// Output: f32[4,128,128,32].
// ---------------------------------------------------------------------------
extern "C" void kernel_launch(void* const* d_in, const int* in_sizes, int n_in,
                              void* d_out, int out_size) {
    const float* feat = (const float*)d_in[0];
    const float* geo  = (const float*)d_in[1];
    const float* W1   = (const float*)d_in[2];
    const float* W2   = (const float*)d_in[3];
    const void*  nrm  = (n_in > 4) ? d_in[4] : nullptr;
    float* out = (float*)d_out;

    k_partial<<<BZ * NN + 9, 256>>>(feat, geo, W1, W2);
    k_middle<<<BZ, 512>>>(geo);
    k_expand<<<BZ * NN, 256>>>(geo, out, nrm);
}